// round 3
// baseline (speedup 1.0000x reference)
#include <cuda_runtime.h>
#include <cstdint>

typedef unsigned long long u64;

// ---------------- device scratch (no allocations allowed) ----------------
__device__ float g_part_edge[160][64];
__device__ float g_part_node[160][64];
__device__ float g_zhist[64];
__device__ float g_base[64];
__device__ float g_av[64];
__device__ float g_bv[64];
__device__ float g_w2v[64];

// ---------------- f32x2 packed helpers ------------------------------------
__device__ __forceinline__ u64 pk2(float a, float b) {
    u64 r; asm("mov.b64 %0,{%1,%2};" : "=l"(r) : "f"(a), "f"(b)); return r;
}
__device__ __forceinline__ void up2(u64 v, float& a, float& b) {
    asm("mov.b64 {%0,%1},%2;" : "=f"(a), "=f"(b) : "l"(v));
}
__device__ __forceinline__ u64 f2fma(u64 a, u64 b, u64 c) {
    u64 d; asm("fma.rn.f32x2 %0,%1,%2,%3;" : "=l"(d) : "l"(a), "l"(b), "l"(c)); return d;
}
__device__ __forceinline__ u64 add2(u64 a, u64 b) {
    u64 d; asm("add.rn.f32x2 %0,%1,%2;" : "=l"(d) : "l"(a), "l"(b)); return d;
}
__device__ __forceinline__ u64 relu2(u64 v) {
    u64 r;
    asm("{\n\t.reg .f32 l,h;\n\t"
        "mov.b64 {l,h}, %1;\n\t"
        "max.f32 l, l, 0f00000000;\n\t"
        "max.f32 h, h, 0f00000000;\n\t"
        "mov.b64 %0, {l,h};\n\t}"
        : "=l"(r) : "l"(v));
    return r;
}
__device__ __forceinline__ float tanh_ap(float x) {
    float r; asm("tanh.approx.f32 %0,%1;" : "=f"(r) : "f"(x)); return r;
}
__device__ __forceinline__ float sigm(float x) { return 1.f / (1.f + __expf(-x)); }

#define NTH  1024
#define RPS  1024
#define REDP 66     // padded row-slice stride in red[]

// ---------------- staged MLP mean-pool reduction --------------------------
// 1024 threads. Group of 16 threads (tid&15) -> 4 outputs each (64 total).
// f32x2 lanes = (output j, output j+1): weights load as natural float2 pairs
// (no duplication), x comes from shared pre-DUPLICATED as (x,x) u64 pairs
// (staging addr = 8*f, perfectly linear/coalesced, zero index math).
template<int INF>
__device__ __forceinline__ void phase(const float* __restrict__ X,
                                      const float* __restrict__ W,
                                      const float* __restrict__ bias,
                                      int nrows, float* __restrict__ partial,
                                      int nb, int b,
                                      u64* __restrict__ dbuf,   // 2 * RPS * INF u64
                                      float* __restrict__ red)  // 64*REDP floats
{
    const int tid = threadIdx.x;
    const int j0 = (tid & 15) * 4;
    const int rs = tid >> 4;        // row-slice 0..63

    u64 w2[INF * 2];
    u64 b2[2];
#pragma unroll
    for (int k = 0; k < INF; k++) {
        float2 p0 = *(const float2*)(W + k * 64 + j0);
        float2 p1 = *(const float2*)(W + k * 64 + j0 + 2);
        w2[k * 2]     = pk2(p0.x, p0.y);
        w2[k * 2 + 1] = pk2(p1.x, p1.y);
    }
    {
        float2 q0 = *(const float2*)(bias + j0);
        float2 q1 = *(const float2*)(bias + j0 + 2);
        b2[0] = pk2(q0.x, q0.y);
        b2[1] = pk2(q1.x, q1.y);
    }
    u64 acc0 = 0ull, acc1 = 0ull;

    const int nstages = (nrows + RPS - 1) >> 10;
    const int nelem = nrows * INF;
    float pf[INF];

    __syncthreads();   // protect dbuf against previous phase's readers
    if (b < nstages) {
        const int e0 = b * (RPS * INF);
#pragma unroll
        for (int c = 0; c < INF; c++) {
            const int e = e0 + tid + c * NTH;
            pf[c] = (e < nelem) ? X[e] : 0.f;
        }
#pragma unroll
        for (int c = 0; c < INF; c++)
            dbuf[tid + c * NTH] = pk2(pf[c], pf[c]);
        if (b + nb < nstages) {
            const int e1 = (b + nb) * (RPS * INF);
#pragma unroll
            for (int c = 0; c < INF; c++) {
                const int e = e1 + tid + c * NTH;
                pf[c] = (e < nelem) ? X[e] : 0.f;
            }
        }
    }

    int p = 0;
    for (int s = b; s < nstages; s += nb) {
        __syncthreads();    // buf[p] stores visible; buf[p^1] free to write
        const u64* buf = dbuf + p * (RPS * INF);
        const int rows = min(RPS, nrows - (s << 10));

        if (rows == RPS) {
#pragma unroll 1
            for (int it = 0; it < RPS / 64; it++) {
                const u64* xp = buf + (it * 64 + rs) * INF;
                u64 x[INF];
#pragma unroll
                for (int k = 0; k < INF; k++) x[k] = xp[k];
                u64 y0 = b2[0], y1 = b2[1];
#pragma unroll
                for (int k = 0; k < INF; k++) {
                    y0 = f2fma(x[k], w2[k * 2],     y0);
                    y1 = f2fma(x[k], w2[k * 2 + 1], y1);
                }
                acc0 = add2(relu2(y0), acc0);
                acc1 = add2(relu2(y1), acc1);
            }
        } else {
#pragma unroll 1
            for (int it = 0; it < RPS / 64; it++) {
                const int rl = it * 64 + rs;
                const u64* xp = buf + rl * INF;
                u64 x[INF];
#pragma unroll
                for (int k = 0; k < INF; k++) x[k] = xp[k];
                const float m = (rl < rows) ? 1.f : 0.f;
                const u64 m2 = pk2(m, m);
                u64 y0 = b2[0], y1 = b2[1];
#pragma unroll
                for (int k = 0; k < INF; k++) {
                    y0 = f2fma(x[k], w2[k * 2],     y0);
                    y1 = f2fma(x[k], w2[k * 2 + 1], y1);
                }
                acc0 = f2fma(relu2(y0), m2, acc0);
                acc1 = f2fma(relu2(y1), m2, acc1);
            }
        }

        // store next stage (different buffer) and prefetch the one after
        if (s + nb < nstages) {
            u64* bufn = dbuf + (p ^ 1) * (RPS * INF);
#pragma unroll
            for (int c = 0; c < INF; c++)
                bufn[tid + c * NTH] = pk2(pf[c], pf[c]);
            if (s + 2 * nb < nstages) {
                const int e2 = (s + 2 * nb) * (RPS * INF);
#pragma unroll
                for (int c = 0; c < INF; c++) {
                    const int e = e2 + tid + c * NTH;
                    pf[c] = (e < nelem) ? X[e] : 0.f;
                }
            }
        }
        p ^= 1;
    }

    // deterministic cross-thread reduce: 64 row-slices x 64 outputs
    __syncthreads();
    {
        float o0, o1, o2, o3;
        up2(acc0, o0, o1); up2(acc1, o2, o3);
        red[rs * REDP + j0 + 0] = o0;
        red[rs * REDP + j0 + 1] = o1;
        red[rs * REDP + j0 + 2] = o2;
        red[rs * REDP + j0 + 3] = o3;
    }
    __syncthreads();
    if (tid < 64) {
        float sum = 0.f;
#pragma unroll 8
        for (int r2 = 0; r2 < 64; r2++) sum += red[r2 * REDP + tid];
        partial[tid] = sum;
    }
}

// ---------------- kernel 1: LSTM (block 0) + node/edge reduce -------------
// dynamic shared layout (bytes):
//   [0,           81920)  : dbuf  (2 * 1024 * 5 u64)
//   [81920,       98816)  : red   (64*66 floats)
//   [98816,      101248)  : sh_hist (608 floats)
//   [101248,     102272)  : sh_g  (256 floats)
//   [102272,     102528)  : sh_h  (64 floats, 8B aligned)
#define K1_SMEM 102528

extern __shared__ __align__(16) char dsm_raw[];

__global__ void __launch_bounds__(1024, 1) k1(
    const float* __restrict__ node, const float* __restrict__ edge,
    const float* __restrict__ hist, int Nn, int Ne, int T,
    const float* __restrict__ nodeW, const float* __restrict__ nodeb,
    const float* __restrict__ edgeW, const float* __restrict__ edgeb,
    const float* __restrict__ Wih, const float* __restrict__ Whh,
    const float* __restrict__ bih, const float* __restrict__ bhh)
{
    u64*   dbuf    = (u64*)dsm_raw;
    float* red     = (float*)(dsm_raw + 81920);
    float* sh_hist = red + 64 * REDP;
    float* sh_g    = sh_hist + 608;
    float* sh_h    = sh_g + 256;

    const int tid = threadIdx.x;

    if (blockIdx.x == 0) {
        // ---------------- LSTM: 256 gate threads (of 1024) ----------------
        u64 w2[32];
        float wi0 = 0.f, wi1 = 0.f, wi2 = 0.f, bsum = 0.f;
        if (tid < 256) {
            const float2* wr = (const float2*)(Whh + tid * 64);
#pragma unroll
            for (int k = 0; k < 32; k++) { float2 pp = wr[k]; w2[k] = pk2(pp.x, pp.y); }
            wi0 = Wih[tid * 3]; wi1 = Wih[tid * 3 + 1]; wi2 = Wih[tid * 3 + 2];
            bsum = bih[tid] + bhh[tid];
        }
        const bool hsh = (T * 3 <= 608);
        for (int i = tid; i < T * 3 && i < 608; i += 1024) sh_hist[i] = hist[i];
        if (tid < 64) sh_h[tid] = 0.f;
        float c = 0.f;
        __syncthreads();

        const bool is_tanh_gate = (tid >= 128 && tid < 192);
        for (int t = 0; t < T; t++) {
            if (tid < 256) {
                const float* xp = hsh ? (sh_hist + t * 3) : (hist + t * 3);
                float pre = fmaf(wi0, xp[0], fmaf(wi1, xp[1], fmaf(wi2, xp[2], bsum)));
                const u64* hp = (const u64*)sh_h;
                u64 a0 = 0, a1 = 0, a2 = 0, a3 = 0;
#pragma unroll
                for (int k = 0; k < 32; k += 4) {
                    a0 = f2fma(w2[k],     hp[k],     a0);
                    a1 = f2fma(w2[k + 1], hp[k + 1], a1);
                    a2 = f2fma(w2[k + 2], hp[k + 2], a2);
                    a3 = f2fma(w2[k + 3], hp[k + 3], a3);
                }
                float s0, s1, s2, s3, s4, s5, s6, s7;
                up2(a0, s0, s1); up2(a1, s2, s3); up2(a2, s4, s5); up2(a3, s6, s7);
                const float z = pre + ((s0 + s1) + (s2 + s3)) + ((s4 + s5) + (s6 + s7));
                sh_g[tid] = is_tanh_gate ? tanh_ap(z) : sigm(z);
            }
            __syncthreads();
            if (tid < 64) {
                const float ig = sh_g[tid], fg = sh_g[64 + tid];
                const float gg = sh_g[128 + tid], og = sh_g[192 + tid];
                c = fmaf(fg, c, ig * gg);
                sh_h[tid] = og * tanh_ap(c);
            }
            __syncthreads();
        }
        if (tid < 64) g_zhist[tid] = sh_h[tid];
    } else {
        const int b = blockIdx.x - 1;
        const int nb = gridDim.x - 1;
        phase<2>(node, nodeW, nodeb, Nn, g_part_node[b], nb, b, dbuf, red);
        phase<5>(edge, edgeW, edgeb, Ne, g_part_edge[b], nb, b, dbuf, red);
    }
}

// ---------------- kernel 2: finalize ctx + precompute base/a/b/w2 ---------
__global__ void __launch_bounds__(256) k2(int nb, int Nn, int Ne,
                   const float* __restrict__ W1, const float* __restrict__ b1,
                   const float* __restrict__ W2f)
{
    __shared__ float ctx[192];
    __shared__ float t1[256], t2[256];
    const int tid = threadIdx.x;
    const int c = tid >> 6, j = tid & 63;

    float se = 0.f, sn = 0.f;
    for (int b = c; b < nb; b += 4) {
        se += g_part_edge[b][j];
        sn += g_part_node[b][j];
    }
    t1[tid] = se; t2[tid] = sn;
    __syncthreads();
    if (tid < 64) {
        const float e = t1[tid] + t1[tid + 64] + t1[tid + 128] + t1[tid + 192];
        const float n = t2[tid] + t2[tid + 64] + t2[tid + 128] + t2[tid + 192];
        ctx[tid]       = n * (1.f / (float)Nn);
        ctx[64 + tid]  = e * (1.f / (float)Ne);
        ctx[128 + tid] = g_zhist[tid];
    }
    __syncthreads();
    float p = 0.f;
    const int i0 = c * 48;
#pragma unroll 8
    for (int i = i0; i < i0 + 48; i++) p = fmaf(ctx[i], W1[i * 64 + j], p);
    __syncthreads();
    t1[tid] = p;
    __syncthreads();
    if (tid < 64) {
        g_base[tid] = b1[tid] + ((t1[tid] + t1[tid + 64]) + (t1[tid + 128] + t1[tid + 192]));
        g_av[tid]   = W1[192 * 64 + tid];
        g_bv[tid]   = W1[193 * 64 + tid];
        g_w2v[tid]  = W2f[tid];
    }
}

// ---------------- kernel 3: candidate scoring (ILP=8, shared wt reuse) ----
__global__ void __launch_bounds__(256) k3(const int* __restrict__ cand, int P,
                                          const int* __restrict__ Np,
                                          const float* __restrict__ fb2,
                                          float* __restrict__ out)
{
    __shared__ __align__(16) u64 s4[128];   // [jp]{base2, a2, b2, w22}
    const int tid = threadIdx.x;
    if (tid < 32) {
        s4[tid * 4 + 0] = pk2(g_base[2 * tid], g_base[2 * tid + 1]);
        s4[tid * 4 + 1] = pk2(g_av[2 * tid],   g_av[2 * tid + 1]);
        s4[tid * 4 + 2] = pk2(g_bv[2 * tid],   g_bv[2 * tid + 1]);
        s4[tid * 4 + 3] = pk2(g_w2v[2 * tid],  g_w2v[2 * tid + 1]);
    }
    const float invd = 1.f / ((float)(*Np) - 1.f + 1e-9f);
    const float bias2 = fb2[0];
    __syncthreads();

    const int p0 = blockIdx.x * 2048 + tid;
    u64 cx2[8], cy2[8];
#pragma unroll
    for (int i = 0; i < 8; i++) {
        const int p = p0 + i * 256;
        float cx = 0.f, cy = 0.f;
        if (p < P) {
            const int2 cp = ((const int2*)cand)[p];
            cx = (float)cp.x * invd;
            cy = (float)cp.y * invd;
        }
        cx2[i] = pk2(cx, cx);
        cy2[i] = pk2(cy, cy);
    }

    u64 acc[8] = {0, 0, 0, 0, 0, 0, 0, 0};
#pragma unroll 8
    for (int jp = 0; jp < 32; jp++) {
        const u64 bb = s4[jp * 4 + 0];
        const u64 aa = s4[jp * 4 + 1];
        const u64 bv = s4[jp * 4 + 2];
        const u64 ww = s4[jp * 4 + 3];
#pragma unroll
        for (int i = 0; i < 8; i++) {
            u64 tt = f2fma(cx2[i], aa, bb);
            tt = f2fma(cy2[i], bv, tt);
            acc[i] = f2fma(relu2(tt), ww, acc[i]);
        }
    }
#pragma unroll
    for (int i = 0; i < 8; i++) {
        const int p = p0 + i * 256;
        if (p < P) {
            float l, h; up2(acc[i], l, h);
            out[p] = l + h + bias2;
        }
    }
}

// ---------------- launch ---------------------------------------------------
extern "C" void kernel_launch(void* const* d_in, const int* in_sizes, int n_in,
                              void* d_out, int out_size)
{
    const float* node  = (const float*)d_in[0];
    const float* edge  = (const float*)d_in[1];
    const float* hist  = (const float*)d_in[2];
    const int*   cand  = (const int*)d_in[3];
    const int*   Np    = (const int*)d_in[4];
    const float* nodeW = (const float*)d_in[5];
    const float* nodeb = (const float*)d_in[6];
    const float* edgeW = (const float*)d_in[7];
    const float* edgeb = (const float*)d_in[8];
    const float* Wih   = (const float*)d_in[9];
    const float* Whh   = (const float*)d_in[10];
    const float* bih   = (const float*)d_in[11];
    const float* bhh   = (const float*)d_in[12];
    const float* fW1   = (const float*)d_in[13];
    const float* fb1   = (const float*)d_in[14];
    const float* fW2   = (const float*)d_in[15];
    const float* fb2   = (const float*)d_in[16];

    const int Nn = in_sizes[0] / 2;
    const int Ne = in_sizes[1] / 5;
    const int T  = in_sizes[2] / 3;
    const int P  = in_sizes[3] / 2;

    static bool attr_set = false;
    if (!attr_set) {
        cudaFuncSetAttribute(k1, cudaFuncAttributeMaxDynamicSharedMemorySize, K1_SMEM);
        attr_set = true;
    }

    const int GRID1 = 148;  // block 0 = LSTM, 147 = node/edge reduce
    k1<<<GRID1, 1024, K1_SMEM>>>(node, edge, hist, Nn, Ne, T,
                                 nodeW, nodeb, edgeW, edgeb, Wih, Whh, bih, bhh);
    k2<<<1, 256>>>(GRID1 - 1, Nn, Ne, fW1, fb1, fW2);
    const int g3 = (P + 2047) / 2048;
    k3<<<g3, 256>>>(cand, P, Np, fb2, (float*)d_out);
}

// round 4
// speedup vs baseline: 1.1660x; 1.1660x over previous
#include <cuda_runtime.h>
#include <cstdint>

typedef unsigned long long u64;

// ---------------- device scratch (no allocations allowed) ----------------
__device__ float g_part_edge[160][64];
__device__ float g_part_node[160][64];
__device__ float g_zhist[64];
__device__ float g_base[64];
__device__ float g_av[64];
__device__ float g_bv[64];
__device__ float g_w2v[64];

// ---------------- f32x2 packed helpers ------------------------------------
__device__ __forceinline__ u64 pk2(float a, float b) {
    u64 r; asm("mov.b64 %0,{%1,%2};" : "=l"(r) : "f"(a), "f"(b)); return r;
}
__device__ __forceinline__ void up2(u64 v, float& a, float& b) {
    asm("mov.b64 {%0,%1},%2;" : "=f"(a), "=f"(b) : "l"(v));
}
__device__ __forceinline__ u64 f2fma(u64 a, u64 b, u64 c) {
    u64 d; asm("fma.rn.f32x2 %0,%1,%2,%3;" : "=l"(d) : "l"(a), "l"(b), "l"(c)); return d;
}
__device__ __forceinline__ u64 add2(u64 a, u64 b) {
    u64 d; asm("add.rn.f32x2 %0,%1,%2;" : "=l"(d) : "l"(a), "l"(b)); return d;
}
__device__ __forceinline__ u64 relu2(u64 v) {
    u64 r;
    asm("{\n\t.reg .f32 l,h;\n\t"
        "mov.b64 {l,h}, %1;\n\t"
        "max.f32 l, l, 0f00000000;\n\t"
        "max.f32 h, h, 0f00000000;\n\t"
        "mov.b64 %0, {l,h};\n\t}"
        : "=l"(r) : "l"(v));
    return r;
}
__device__ __forceinline__ float tanh_ap(float x) {
    float r; asm("tanh.approx.f32 %0,%1;" : "=f"(r) : "f"(x)); return r;
}
__device__ __forceinline__ float sigm(float x) { return 1.f / (1.f + __expf(-x)); }

#define NTH    1024
#define RPS    1024          // rows per stage
#define KPADF  1058          // padded float stride per input-feature column
#define REDW   68            // padded per-warp stride in red[]

// ---- dynamic shared layout (bytes), union of two uses --------------------
//  phase:  dbuf  [0, 42320)          2 buffers x INF(<=5)*KPADF floats
//          red   [42320, 51024)      32*68 floats
//  LSTM :  whh   [0, 67584)          256 rows x 66 floats (u64-aligned rows)
//          hist  [67584, 70016)      608 floats
//          shg   [70016, 71040)      256 floats
//          shh   [71040, 71296)      64 floats (8B aligned)
#define K1_SMEM 71296

extern __shared__ __align__(16) char dsm_raw[];

// ---------------- staged MLP mean-pool reduction --------------------------
// 1024 threads. lane = output pair index (j0 = 2*lane), warp = row-slice.
// f32x2 lanes = (row 2rp, row 2rp+1). All 32 lanes of a warp read the SAME
// shared address (broadcast LDS.64). Shared layout transposed: sf[k][row].
template<int INF>
__device__ __forceinline__ void phase(const float* __restrict__ X,
                                      const float* __restrict__ W,
                                      const float* __restrict__ bias,
                                      int nrows, float* __restrict__ partial,
                                      int nb, int b)
{
    float* sf  = (float*)dsm_raw;                 // 2 * INF * KPADF floats
    float* red = (float*)(dsm_raw + 42320);
    const int tid  = threadIdx.x;
    const int lane = tid & 31;
    const int w    = tid >> 5;                    // 0..31 row-slice
    const int j0   = lane * 2;
    const int BUFS = INF * KPADF;                 // floats per buffer

    u64 w2[INF * 2];
    u64 b2[2];
#pragma unroll
    for (int k = 0; k < INF; k++) {
        float wa = W[k * 64 + j0];
        float wb = W[k * 64 + j0 + 1];
        w2[k * 2]     = pk2(wa, wa);
        w2[k * 2 + 1] = pk2(wb, wb);
    }
    {
        float ba = bias[j0], bb = bias[j0 + 1];
        b2[0] = pk2(ba, ba);
        b2[1] = pk2(bb, bb);
    }
    u64 acc0 = 0ull, acc1 = 0ull;

    const int nstages = (nrows + RPS - 1) >> 10;
    const int nelem = nrows * INF;
    float pf[INF];

    __syncthreads();   // protect shared against previous phase's readers
    if (b < nstages) {
        // stage b: load + store directly
        const int e0 = b * (RPS * INF);
#pragma unroll
        for (int c = 0; c < INF; c++) {
            const int e = e0 + tid + c * NTH;
            pf[c] = (e < nelem) ? X[e] : 0.f;
        }
#pragma unroll
        for (int c = 0; c < INF; c++) {
            const int e = tid + c * NTH;          // local element in stage
            const int row = e / INF;
            const int k = e - row * INF;
            sf[k * KPADF + row] = pf[c];
        }
        // prefetch stage b+nb
        if (b + nb < nstages) {
            const int e1 = (b + nb) * (RPS * INF);
#pragma unroll
            for (int c = 0; c < INF; c++) {
                const int e = e1 + tid + c * NTH;
                pf[c] = (e < nelem) ? X[e] : 0.f;
            }
        }
    }

    int p = 0;
    for (int s = b; s < nstages; s += nb) {
        __syncthreads();
        const u64* buf = (const u64*)(sf + p * BUFS);
        const int rows = min(RPS, nrows - (s << 10));

        if (rows == RPS) {
#pragma unroll 4
            for (int it = 0; it < 16; it++) {
                const int rp = it * 32 + w;
                u64 y0 = b2[0], y1 = b2[1];
#pragma unroll
                for (int k = 0; k < INF; k++) {
                    const u64 x = buf[k * (KPADF / 2) + rp];
                    y0 = f2fma(x, w2[k * 2],     y0);
                    y1 = f2fma(x, w2[k * 2 + 1], y1);
                }
                acc0 = add2(relu2(y0), acc0);
                acc1 = add2(relu2(y1), acc1);
            }
        } else {
#pragma unroll 4
            for (int it = 0; it < 16; it++) {
                const int rp = it * 32 + w;
                const float m0 = (2 * rp < rows) ? 1.f : 0.f;
                const float m1 = (2 * rp + 1 < rows) ? 1.f : 0.f;
                const u64 m2 = pk2(m0, m1);
                u64 y0 = b2[0], y1 = b2[1];
#pragma unroll
                for (int k = 0; k < INF; k++) {
                    const u64 x = buf[k * (KPADF / 2) + rp];
                    y0 = f2fma(x, w2[k * 2],     y0);
                    y1 = f2fma(x, w2[k * 2 + 1], y1);
                }
                acc0 = f2fma(relu2(y0), m2, acc0);
                acc1 = f2fma(relu2(y1), m2, acc1);
            }
        }

        // stage s+nb into other buffer; prefetch s+2nb
        if (s + nb < nstages) {
            float* sfn = sf + (p ^ 1) * BUFS;
#pragma unroll
            for (int c = 0; c < INF; c++) {
                const int e = tid + c * NTH;
                const int row = e / INF;
                const int k = e - row * INF;
                sfn[k * KPADF + row] = pf[c];
            }
            if (s + 2 * nb < nstages) {
                const int e2 = (s + 2 * nb) * (RPS * INF);
#pragma unroll
                for (int c = 0; c < INF; c++) {
                    const int e = e2 + tid + c * NTH;
                    pf[c] = (e < nelem) ? X[e] : 0.f;
                }
            }
        }
        p ^= 1;
    }

    // deterministic cross-warp reduce: 32 warps x 64 outputs
    __syncthreads();
    {
        float a0l, a0h, a1l, a1h;
        up2(acc0, a0l, a0h); up2(acc1, a1l, a1h);
        red[w * REDW + j0]     = a0l + a0h;
        red[w * REDW + j0 + 1] = a1l + a1h;
    }
    __syncthreads();
    if (tid < 64) {
        float sum = 0.f;
#pragma unroll 8
        for (int r2 = 0; r2 < 32; r2++) sum += red[r2 * REDW + tid];
        partial[tid] = sum;
    }
}

// ---------------- kernel 1: LSTM (block 0) + node/edge reduce -------------
__global__ void __launch_bounds__(1024, 1) k1(
    const float* __restrict__ node, const float* __restrict__ edge,
    const float* __restrict__ hist, int Nn, int Ne, int T,
    const float* __restrict__ nodeW, const float* __restrict__ nodeb,
    const float* __restrict__ edgeW, const float* __restrict__ edgeb,
    const float* __restrict__ Wih, const float* __restrict__ Whh,
    const float* __restrict__ bih, const float* __restrict__ bhh)
{
    const int tid = threadIdx.x;

    if (blockIdx.x == 0) {
        // ---------------- LSTM: Whh in shared (no reg pressure) ----------
        float* whh_f   = (float*)dsm_raw;               // 256 x 66 floats
        float* sh_hist = (float*)(dsm_raw + 67584);
        float* sh_g    = (float*)(dsm_raw + 70016);
        float* sh_h    = (float*)(dsm_raw + 71040);

        for (int e = tid; e < 256 * 64; e += NTH) {
            const int r = e >> 6, kf = e & 63;
            whh_f[r * 66 + kf] = Whh[e];
        }
        float wi0 = 0.f, wi1 = 0.f, wi2 = 0.f, bsum = 0.f;
        if (tid < 256) {
            wi0 = Wih[tid * 3]; wi1 = Wih[tid * 3 + 1]; wi2 = Wih[tid * 3 + 2];
            bsum = bih[tid] + bhh[tid];
        }
        const bool hsh = (T * 3 <= 608);
        for (int i = tid; i < T * 3 && i < 608; i += NTH) sh_hist[i] = hist[i];
        if (tid < 64) sh_h[tid] = 0.f;
        float c = 0.f;
        __syncthreads();

        const u64* wrow = (const u64*)(whh_f) + tid * 33;  // valid when tid<256
        const bool is_tanh_gate = (tid >= 128 && tid < 192);
        for (int t = 0; t < T; t++) {
            if (tid < 256) {
                const float* xp = hsh ? (sh_hist + t * 3) : (hist + t * 3);
                float pre = fmaf(wi0, xp[0], fmaf(wi1, xp[1], fmaf(wi2, xp[2], bsum)));
                const u64* hp = (const u64*)sh_h;
                u64 a0 = 0, a1 = 0, a2 = 0, a3 = 0;
#pragma unroll
                for (int k = 0; k < 32; k += 4) {
                    a0 = f2fma(wrow[k],     hp[k],     a0);
                    a1 = f2fma(wrow[k + 1], hp[k + 1], a1);
                    a2 = f2fma(wrow[k + 2], hp[k + 2], a2);
                    a3 = f2fma(wrow[k + 3], hp[k + 3], a3);
                }
                float s0, s1, s2, s3, s4, s5, s6, s7;
                up2(a0, s0, s1); up2(a1, s2, s3); up2(a2, s4, s5); up2(a3, s6, s7);
                const float z = pre + ((s0 + s1) + (s2 + s3)) + ((s4 + s5) + (s6 + s7));
                sh_g[tid] = is_tanh_gate ? tanh_ap(z) : sigm(z);
            }
            __syncthreads();
            if (tid < 64) {
                const float ig = sh_g[tid], fg = sh_g[64 + tid];
                const float gg = sh_g[128 + tid], og = sh_g[192 + tid];
                c = fmaf(fg, c, ig * gg);
                sh_h[tid] = og * tanh_ap(c);
            }
            __syncthreads();
        }
        if (tid < 64) g_zhist[tid] = sh_h[tid];
    } else {
        const int b = blockIdx.x - 1;
        const int nb = gridDim.x - 1;
        phase<2>(node, nodeW, nodeb, Nn, g_part_node[b], nb, b);
        phase<5>(edge, edgeW, edgeb, Ne, g_part_edge[b], nb, b);
    }
}

// ---------------- kernel 2: finalize ctx + precompute base/a/b/w2 ---------
__global__ void __launch_bounds__(256) k2(int nb, int Nn, int Ne,
                   const float* __restrict__ W1, const float* __restrict__ b1,
                   const float* __restrict__ W2f)
{
    __shared__ float ctx[192];
    __shared__ float t1[256], t2[256];
    const int tid = threadIdx.x;
    const int c = tid >> 6, j = tid & 63;

    float se = 0.f, sn = 0.f;
    for (int b = c; b < nb; b += 4) {
        se += g_part_edge[b][j];
        sn += g_part_node[b][j];
    }
    t1[tid] = se; t2[tid] = sn;
    __syncthreads();
    if (tid < 64) {
        const float e = t1[tid] + t1[tid + 64] + t1[tid + 128] + t1[tid + 192];
        const float n = t2[tid] + t2[tid + 64] + t2[tid + 128] + t2[tid + 192];
        ctx[tid]       = n * (1.f / (float)Nn);
        ctx[64 + tid]  = e * (1.f / (float)Ne);
        ctx[128 + tid] = g_zhist[tid];
    }
    __syncthreads();
    float p = 0.f;
    const int i0 = c * 48;
#pragma unroll 8
    for (int i = i0; i < i0 + 48; i++) p = fmaf(ctx[i], W1[i * 64 + j], p);
    __syncthreads();
    t1[tid] = p;
    __syncthreads();
    if (tid < 64) {
        g_base[tid] = b1[tid] + ((t1[tid] + t1[tid + 64]) + (t1[tid + 128] + t1[tid + 192]));
        g_av[tid]   = W1[192 * 64 + tid];
        g_bv[tid]   = W1[193 * 64 + tid];
        g_w2v[tid]  = W2f[tid];
    }
}

// ---------------- kernel 3: candidate scoring (ILP=8, shared wt reuse) ----
__global__ void __launch_bounds__(256) k3(const int* __restrict__ cand, int P,
                                          const int* __restrict__ Np,
                                          const float* __restrict__ fb2,
                                          float* __restrict__ out)
{
    __shared__ __align__(16) u64 s4[128];   // [jp]{base2, a2, b2, w22}
    const int tid = threadIdx.x;
    if (tid < 32) {
        s4[tid * 4 + 0] = pk2(g_base[2 * tid], g_base[2 * tid + 1]);
        s4[tid * 4 + 1] = pk2(g_av[2 * tid],   g_av[2 * tid + 1]);
        s4[tid * 4 + 2] = pk2(g_bv[2 * tid],   g_bv[2 * tid + 1]);
        s4[tid * 4 + 3] = pk2(g_w2v[2 * tid],  g_w2v[2 * tid + 1]);
    }
    const float invd = 1.f / ((float)(*Np) - 1.f + 1e-9f);
    const float bias2 = fb2[0];
    __syncthreads();

    const int p0 = blockIdx.x * 2048 + tid;
    u64 cx2[8], cy2[8];
#pragma unroll
    for (int i = 0; i < 8; i++) {
        const int p = p0 + i * 256;
        float cx = 0.f, cy = 0.f;
        if (p < P) {
            const int2 cp = ((const int2*)cand)[p];
            cx = (float)cp.x * invd;
            cy = (float)cp.y * invd;
        }
        cx2[i] = pk2(cx, cx);
        cy2[i] = pk2(cy, cy);
    }

    u64 acc[8] = {0, 0, 0, 0, 0, 0, 0, 0};
#pragma unroll 8
    for (int jp = 0; jp < 32; jp++) {
        const u64 bb = s4[jp * 4 + 0];
        const u64 aa = s4[jp * 4 + 1];
        const u64 bv = s4[jp * 4 + 2];
        const u64 ww = s4[jp * 4 + 3];
#pragma unroll
        for (int i = 0; i < 8; i++) {
            u64 tt = f2fma(cx2[i], aa, bb);
            tt = f2fma(cy2[i], bv, tt);
            acc[i] = f2fma(relu2(tt), ww, acc[i]);
        }
    }
#pragma unroll
    for (int i = 0; i < 8; i++) {
        const int p = p0 + i * 256;
        if (p < P) {
            float l, h; up2(acc[i], l, h);
            out[p] = l + h + bias2;
        }
    }
}

// ---------------- launch ---------------------------------------------------
extern "C" void kernel_launch(void* const* d_in, const int* in_sizes, int n_in,
                              void* d_out, int out_size)
{
    const float* node  = (const float*)d_in[0];
    const float* edge  = (const float*)d_in[1];
    const float* hist  = (const float*)d_in[2];
    const int*   cand  = (const int*)d_in[3];
    const int*   Np    = (const int*)d_in[4];
    const float* nodeW = (const float*)d_in[5];
    const float* nodeb = (const float*)d_in[6];
    const float* edgeW = (const float*)d_in[7];
    const float* edgeb = (const float*)d_in[8];
    const float* Wih   = (const float*)d_in[9];
    const float* Whh   = (const float*)d_in[10];
    const float* bih   = (const float*)d_in[11];
    const float* bhh   = (const float*)d_in[12];
    const float* fW1   = (const float*)d_in[13];
    const float* fb1   = (const float*)d_in[14];
    const float* fW2   = (const float*)d_in[15];
    const float* fb2   = (const float*)d_in[16];

    const int Nn = in_sizes[0] / 2;
    const int Ne = in_sizes[1] / 5;
    const int T  = in_sizes[2] / 3;
    const int P  = in_sizes[3] / 2;

    static bool attr_set = false;
    if (!attr_set) {
        cudaFuncSetAttribute(k1, cudaFuncAttributeMaxDynamicSharedMemorySize, K1_SMEM);
        attr_set = true;
    }

    const int GRID1 = 148;  // block 0 = LSTM, 147 = node/edge reduce
    k1<<<GRID1, NTH, K1_SMEM>>>(node, edge, hist, Nn, Ne, T,
                                nodeW, nodeb, edgeW, edgeb, Wih, Whh, bih, bhh);
    k2<<<1, 256>>>(GRID1 - 1, Nn, Ne, fW1, fb1, fW2);
    const int g3 = (P + 2047) / 2048;
    k3<<<g3, 256>>>(cand, P, Np, fb2, (float*)d_out);
}

// round 5
// speedup vs baseline: 1.2345x; 1.0587x over previous
#include <cuda_runtime.h>
#include <cstdint>

typedef unsigned long long u64;
typedef unsigned int u32;

// ---------------- device scratch (no allocations allowed) ----------------
__device__ float g_part_edge[160][64];
__device__ float g_part_node[160][64];
__device__ float g_zhist[64];
__device__ float g_base[64];
__device__ float g_av[64];
__device__ float g_bv[64];
__device__ float g_w2v[64];

// ---------------- f32x2 packed helpers ------------------------------------
__device__ __forceinline__ u64 pk2(float a, float b) {
    u64 r; asm("mov.b64 %0,{%1,%2};" : "=l"(r) : "f"(a), "f"(b)); return r;
}
__device__ __forceinline__ void up2(u64 v, float& a, float& b) {
    asm("mov.b64 {%0,%1},%2;" : "=f"(a), "=f"(b) : "l"(v));
}
__device__ __forceinline__ u64 f2fma(u64 a, u64 b, u64 c) {
    u64 d; asm("fma.rn.f32x2 %0,%1,%2,%3;" : "=l"(d) : "l"(a), "l"(b), "l"(c)); return d;
}
__device__ __forceinline__ u64 add2(u64 a, u64 b) {
    u64 d; asm("add.rn.f32x2 %0,%1,%2;" : "=l"(d) : "l"(a), "l"(b)); return d;
}
__device__ __forceinline__ u64 relu2(u64 v) {
    u64 r;
    asm("{\n\t.reg .f32 l,h;\n\t"
        "mov.b64 {l,h}, %1;\n\t"
        "max.f32 l, l, 0f00000000;\n\t"
        "max.f32 h, h, 0f00000000;\n\t"
        "mov.b64 %0, {l,h};\n\t}"
        : "=l"(r) : "l"(v));
    return r;
}
__device__ __forceinline__ float tanh_ap(float x) {
    float r; asm("tanh.approx.f32 %0,%1;" : "=f"(r) : "f"(x)); return r;
}
__device__ __forceinline__ float sigm(float x) { return 1.f / (1.f + __expf(-x)); }

// pack two f32 into one b32 holding (lo=a, hi=b) as bf16x2
__device__ __forceinline__ u32 bfpack(float lo, float hi) {
    u32 r; asm("cvt.rn.bf16x2.f32 %0, %1, %2;" : "=r"(r) : "f"(hi), "f"(lo)); return r;
}

// m16n8k8 bf16 mma, fp32 accum
__device__ __forceinline__ void mma8(float& d0, float& d1, float& d2, float& d3,
                                     u32 a0, u32 a1, u32 b,
                                     float c0, float c1, float c2, float c3) {
    asm("mma.sync.aligned.m16n8k8.row.col.f32.bf16.bf16.f32 "
        "{%0,%1,%2,%3},{%4,%5},{%6},{%7,%8,%9,%10};"
        : "=f"(d0), "=f"(d1), "=f"(d2), "=f"(d3)
        : "r"(a0), "r"(a1), "r"(b), "f"(c0), "f"(c1), "f"(c2), "f"(c3));
}

#define NTH    768
#define RPS    1536          // rows per stage
#define ROWB   16            // bytes per staged bf16 row (8 bf16, k-padded)
#define BUFB   (RPS * ROWB)  // 24576 bytes per buffer
#define REDW   68

// ---- dynamic shared layout (bytes), union of two uses --------------------
//  phase:  dbuf  [0, 49152)          2 x 1536 rows x 16B bf16
//          red   [49152, 55680)      24*68 floats
//  LSTM :  whh   [0, 67584)          256 rows x 66 floats
//          hist  [67584, 70016)      608 floats
//          shg   [70016, 71040)      256 floats
//          shh   [71040, 71296)      64 floats
#define K1_SMEM 71296

extern __shared__ __align__(16) char dsm_raw[];

// ---------------- tensor-core MLP mean-pool reduction ---------------------
// 768 threads / 24 warps. Each warp does 4 16-row tiles per stage.
// X staged as bf16 rows of 8 (k padded with zeros), 16B/row.
// Bias enters via mma C operand; relu+mean accum in packed f32x2 registers.
template<int INF>
__device__ __forceinline__ void phase(const float* __restrict__ X,
                                      const float* __restrict__ W,
                                      const float* __restrict__ bias,
                                      int nrows, float* __restrict__ partial,
                                      int nb, int b)
{
    const int tid  = threadIdx.x;
    const int lane = tid & 31;
    const int w    = tid >> 5;          // warp 0..23
    const int gid  = lane >> 2;         // 0..7
    const int tig  = lane & 3;          // 0..3

    // B fragments (col n = gid) and bias C (cols 2*tig, 2*tig+1)
    u32 bf[8];
    float c0[8], c1[8];
#pragma unroll
    for (int nt = 0; nt < 8; nt++) {
        const int ncol = nt * 8 + gid;
        const int klo = 2 * tig, khi = klo + 1;
        const float vlo = (klo < INF) ? W[klo * 64 + ncol] : 0.f;
        const float vhi = (khi < INF) ? W[khi * 64 + ncol] : 0.f;
        bf[nt] = bfpack(vlo, vhi);
        const int dcol = nt * 8 + 2 * tig;
        c0[nt] = bias[dcol];
        c1[nt] = bias[dcol + 1];
    }
    u64 acc[8] = {0, 0, 0, 0, 0, 0, 0, 0};

    const int nstages = (nrows + RPS - 1) / RPS;
    const int rA = tid * 2, rB = rA + 1;   // local staged rows
    float pA[INF], pB[INF];

    __syncthreads();   // protect shared vs previous phase readers

    if (b < nstages) {
        // load + store stage b directly
        {
            const int g0 = b * RPS + rA, g1 = b * RPS + rB;
#pragma unroll
            for (int k = 0; k < INF; k++) {
                pA[k] = (g0 < nrows) ? X[g0 * INF + k] : 0.f;
                pB[k] = (g1 < nrows) ? X[g1 * INF + k] : 0.f;
            }
        }
        {
            u32 qa[4] = {0, 0, 0, 0}, qb[4] = {0, 0, 0, 0};
#pragma unroll
            for (int k = 0; k < 8; k += 2) {
                const float a0 = (k < INF) ? pA[k < INF ? k : 0] : 0.f;
                const float a1 = (k + 1 < INF) ? pA[(k + 1 < INF) ? k + 1 : 0] : 0.f;
                const float b0 = (k < INF) ? pB[k < INF ? k : 0] : 0.f;
                const float b1 = (k + 1 < INF) ? pB[(k + 1 < INF) ? k + 1 : 0] : 0.f;
                qa[k >> 1] = bfpack(a0, a1);
                qb[k >> 1] = bfpack(b0, b1);
            }
            *(uint4*)(dsm_raw + rA * ROWB) = make_uint4(qa[0], qa[1], qa[2], qa[3]);
            *(uint4*)(dsm_raw + rB * ROWB) = make_uint4(qb[0], qb[1], qb[2], qb[3]);
        }
        // prefetch stage b+nb
        if (b + nb < nstages) {
            const int g0 = (b + nb) * RPS + rA, g1 = (b + nb) * RPS + rB;
#pragma unroll
            for (int k = 0; k < INF; k++) {
                pA[k] = (g0 < nrows) ? X[g0 * INF + k] : 0.f;
                pB[k] = (g1 < nrows) ? X[g1 * INF + k] : 0.f;
            }
        }
    }

    int p = 0;
    for (int s = b; s < nstages; s += nb) {
        __syncthreads();
        const char* sb = dsm_raw + p * BUFB;
        const int rows = min(RPS, nrows - s * RPS);

        if (rows == RPS) {
#pragma unroll
            for (int i = 0; i < 4; i++) {
                const int base = (i * 24 + w) * 16;
                const u32 a0 = *(const u32*)(sb + (base + gid) * ROWB + tig * 4);
                const u32 a1 = *(const u32*)(sb + (base + gid + 8) * ROWB + tig * 4);
#pragma unroll
                for (int nt = 0; nt < 8; nt++) {
                    float d0, d1, d2, d3;
                    mma8(d0, d1, d2, d3, a0, a1, bf[nt], c0[nt], c1[nt], c0[nt], c1[nt]);
                    acc[nt] = add2(relu2(pk2(d0, d1)), acc[nt]);
                    acc[nt] = add2(relu2(pk2(d2, d3)), acc[nt]);
                }
            }
        } else {
#pragma unroll
            for (int i = 0; i < 4; i++) {
                const int base = (i * 24 + w) * 16;
                const u32 a0 = *(const u32*)(sb + (base + gid) * ROWB + tig * 4);
                const u32 a1 = *(const u32*)(sb + (base + gid + 8) * ROWB + tig * 4);
                const float m0 = (base + gid < rows) ? 1.f : 0.f;
                const float m1 = (base + gid + 8 < rows) ? 1.f : 0.f;
                const u64 m0p = pk2(m0, m0);
                const u64 m1p = pk2(m1, m1);
#pragma unroll
                for (int nt = 0; nt < 8; nt++) {
                    float d0, d1, d2, d3;
                    mma8(d0, d1, d2, d3, a0, a1, bf[nt], c0[nt], c1[nt], c0[nt], c1[nt]);
                    acc[nt] = f2fma(relu2(pk2(d0, d1)), m0p, acc[nt]);
                    acc[nt] = f2fma(relu2(pk2(d2, d3)), m1p, acc[nt]);
                }
            }
        }

        // stage s+nb into other buffer; prefetch s+2nb
        if (s + nb < nstages) {
            char* sbn = dsm_raw + (p ^ 1) * BUFB;
            u32 qa[4] = {0, 0, 0, 0}, qb[4] = {0, 0, 0, 0};
#pragma unroll
            for (int k = 0; k + 1 < INF; k += 2) {
                qa[k >> 1] = bfpack(pA[k], pA[k + 1]);
                qb[k >> 1] = bfpack(pB[k], pB[k + 1]);
            }
            if (INF & 1) {
                qa[INF >> 1] = bfpack(pA[INF - 1], 0.f);
                qb[INF >> 1] = bfpack(pB[INF - 1], 0.f);
            }
            *(uint4*)(sbn + rA * ROWB) = make_uint4(qa[0], qa[1], qa[2], qa[3]);
            *(uint4*)(sbn + rB * ROWB) = make_uint4(qb[0], qb[1], qb[2], qb[3]);
            if (s + 2 * nb < nstages) {
                const int g0 = (s + 2 * nb) * RPS + rA, g1 = (s + 2 * nb) * RPS + rB;
#pragma unroll
                for (int k = 0; k < INF; k++) {
                    pA[k] = (g0 < nrows) ? X[g0 * INF + k] : 0.f;
                    pB[k] = (g1 < nrows) ? X[g1 * INF + k] : 0.f;
                }
            }
        }
        p ^= 1;
    }

    // reduce: shfl over gid (lanes xor 4,8,16), then cross-warp via shared
    __syncthreads();
    float* red = (float*)(dsm_raw + 2 * BUFB);
#pragma unroll
    for (int nt = 0; nt < 8; nt++) {
        float lo, hi; up2(acc[nt], lo, hi);
#pragma unroll
        for (int off = 4; off <= 16; off <<= 1) {
            lo += __shfl_xor_sync(0xffffffffu, lo, off);
            hi += __shfl_xor_sync(0xffffffffu, hi, off);
        }
        if (gid == 0) {
            red[w * REDW + nt * 8 + 2 * tig]     = lo;
            red[w * REDW + nt * 8 + 2 * tig + 1] = hi;
        }
    }
    __syncthreads();
    if (tid < 64) {
        float sum = 0.f;
#pragma unroll 8
        for (int r2 = 0; r2 < 24; r2++) sum += red[r2 * REDW + tid];
        partial[tid] = sum;
    }
}

// ---------------- kernel 1: LSTM (block 0) + node/edge reduce -------------
__global__ void __launch_bounds__(NTH, 1) k1(
    const float* __restrict__ node, const float* __restrict__ edge,
    const float* __restrict__ hist, int Nn, int Ne, int T,
    const float* __restrict__ nodeW, const float* __restrict__ nodeb,
    const float* __restrict__ edgeW, const float* __restrict__ edgeb,
    const float* __restrict__ Wih, const float* __restrict__ Whh,
    const float* __restrict__ bih, const float* __restrict__ bhh)
{
    const int tid = threadIdx.x;

    if (blockIdx.x == 0) {
        // ---------------- LSTM: Whh in shared, named barriers -------------
        float* whh_f   = (float*)dsm_raw;               // 256 x 66 floats
        float* sh_hist = (float*)(dsm_raw + 67584);
        float* sh_g    = (float*)(dsm_raw + 70016);
        float* sh_h    = (float*)(dsm_raw + 71040);

        for (int e = tid; e < 256 * 64; e += NTH) {
            const int r = e >> 6, kf = e & 63;
            whh_f[r * 66 + kf] = Whh[e];
        }
        for (int i = tid; i < T * 3 && i < 608; i += NTH) sh_hist[i] = hist[i];
        if (tid < 64) sh_h[tid] = 0.f;
        __syncthreads();

        if (tid < 256) {
            const float wi0 = Wih[tid * 3], wi1 = Wih[tid * 3 + 1], wi2 = Wih[tid * 3 + 2];
            const float bsum = bih[tid] + bhh[tid];
            const bool hsh = (T * 3 <= 608);
            const u64* wrow = (const u64*)whh_f + tid * 33;
            const bool is_tanh_gate = (tid >= 128 && tid < 192);
            float c = 0.f;

            for (int t = 0; t < T; t++) {
                const float* xp = hsh ? (sh_hist + t * 3) : (hist + t * 3);
                float pre = fmaf(wi0, xp[0], fmaf(wi1, xp[1], fmaf(wi2, xp[2], bsum)));
                const u64* hp = (const u64*)sh_h;
                u64 a0 = 0, a1 = 0, a2 = 0, a3 = 0;
#pragma unroll
                for (int k = 0; k < 32; k += 4) {
                    a0 = f2fma(wrow[k],     hp[k],     a0);
                    a1 = f2fma(wrow[k + 1], hp[k + 1], a1);
                    a2 = f2fma(wrow[k + 2], hp[k + 2], a2);
                    a3 = f2fma(wrow[k + 3], hp[k + 3], a3);
                }
                float s0, s1, s2, s3, s4, s5, s6, s7;
                up2(a0, s0, s1); up2(a1, s2, s3); up2(a2, s4, s5); up2(a3, s6, s7);
                const float z = pre + ((s0 + s1) + (s2 + s3)) + ((s4 + s5) + (s6 + s7));
                sh_g[tid] = is_tanh_gate ? tanh_ap(z) : sigm(z);
                asm volatile("bar.sync 1, 256;" ::: "memory");
                if (tid < 64) {
                    const float ig = sh_g[tid], fg = sh_g[64 + tid];
                    const float gg = sh_g[128 + tid], og = sh_g[192 + tid];
                    c = fmaf(fg, c, ig * gg);
                    sh_h[tid] = og * tanh_ap(c);
                }
                asm volatile("bar.sync 1, 256;" ::: "memory");
            }
            if (tid < 64) g_zhist[tid] = sh_h[tid];
        }
    } else {
        const int b = blockIdx.x - 1;
        const int nb = gridDim.x - 1;
        phase<2>(node, nodeW, nodeb, Nn, g_part_node[b], nb, b);
        phase<5>(edge, edgeW, edgeb, Ne, g_part_edge[b], nb, b);
    }
}

// ---------------- kernel 2: finalize ctx + precompute base/a/b/w2 ---------
__global__ void __launch_bounds__(256) k2(int nb, int Nn, int Ne,
                   const float* __restrict__ W1, const float* __restrict__ b1,
                   const float* __restrict__ W2f)
{
    __shared__ float ctx[192];
    __shared__ float t1[256], t2[256];
    const int tid = threadIdx.x;
    const int c = tid >> 6, j = tid & 63;

    float se = 0.f, sn = 0.f;
    for (int b = c; b < nb; b += 4) {
        se += g_part_edge[b][j];
        sn += g_part_node[b][j];
    }
    t1[tid] = se; t2[tid] = sn;
    __syncthreads();
    if (tid < 64) {
        const float e = t1[tid] + t1[tid + 64] + t1[tid + 128] + t1[tid + 192];
        const float n = t2[tid] + t2[tid + 64] + t2[tid + 128] + t2[tid + 192];
        ctx[tid]       = n * (1.f / (float)Nn);
        ctx[64 + tid]  = e * (1.f / (float)Ne);
        ctx[128 + tid] = g_zhist[tid];
    }
    __syncthreads();
    float p = 0.f;
    const int i0 = c * 48;
#pragma unroll 8
    for (int i = i0; i < i0 + 48; i++) p = fmaf(ctx[i], W1[i * 64 + j], p);
    __syncthreads();
    t1[tid] = p;
    __syncthreads();
    if (tid < 64) {
        g_base[tid] = b1[tid] + ((t1[tid] + t1[tid + 64]) + (t1[tid + 128] + t1[tid + 192]));
        g_av[tid]   = W1[192 * 64 + tid];
        g_bv[tid]   = W1[193 * 64 + tid];
        g_w2v[tid]  = W2f[tid];
    }
}

// ---------------- kernel 3: candidate scoring (ILP=8, shared wt reuse) ----
__global__ void __launch_bounds__(256) k3(const int* __restrict__ cand, int P,
                                          const int* __restrict__ Np,
                                          const float* __restrict__ fb2,
                                          float* __restrict__ out)
{
    __shared__ __align__(16) u64 s4[128];   // [jp]{base2, a2, b2, w22}
    const int tid = threadIdx.x;
    if (tid < 32) {
        s4[tid * 4 + 0] = pk2(g_base[2 * tid], g_base[2 * tid + 1]);
        s4[tid * 4 + 1] = pk2(g_av[2 * tid],   g_av[2 * tid + 1]);
        s4[tid * 4 + 2] = pk2(g_bv[2 * tid],   g_bv[2 * tid + 1]);
        s4[tid * 4 + 3] = pk2(g_w2v[2 * tid],  g_w2v[2 * tid + 1]);
    }
    const float invd = 1.f / ((float)(*Np) - 1.f + 1e-9f);
    const float bias2 = fb2[0];
    __syncthreads();

    const int p0 = blockIdx.x * 2048 + tid;
    u64 cx2[8], cy2[8];
#pragma unroll
    for (int i = 0; i < 8; i++) {
        const int p = p0 + i * 256;
        float cx = 0.f, cy = 0.f;
        if (p < P) {
            const int2 cp = ((const int2*)cand)[p];
            cx = (float)cp.x * invd;
            cy = (float)cp.y * invd;
        }
        cx2[i] = pk2(cx, cx);
        cy2[i] = pk2(cy, cy);
    }

    u64 acc[8] = {0, 0, 0, 0, 0, 0, 0, 0};
#pragma unroll 8
    for (int jp = 0; jp < 32; jp++) {
        const u64 bb = s4[jp * 4 + 0];
        const u64 aa = s4[jp * 4 + 1];
        const u64 bv = s4[jp * 4 + 2];
        const u64 ww = s4[jp * 4 + 3];
#pragma unroll
        for (int i = 0; i < 8; i++) {
            u64 tt = f2fma(cx2[i], aa, bb);
            tt = f2fma(cy2[i], bv, tt);
            acc[i] = f2fma(relu2(tt), ww, acc[i]);
        }
    }
#pragma unroll
    for (int i = 0; i < 8; i++) {
        const int p = p0 + i * 256;
        if (p < P) {
            float l, h; up2(acc[i], l, h);
            out[p] = l + h + bias2;
        }
    }
}

// ---------------- launch ---------------------------------------------------
extern "C" void kernel_launch(void* const* d_in, const int* in_sizes, int n_in,
                              void* d_out, int out_size)
{
    const float* node  = (const float*)d_in[0];
    const float* edge  = (const float*)d_in[1];
    const float* hist  = (const float*)d_in[2];
    const int*   cand  = (const int*)d_in[3];
    const int*   Np    = (const int*)d_in[4];
    const float* nodeW = (const float*)d_in[5];
    const float* nodeb = (const float*)d_in[6];
    const float* edgeW = (const float*)d_in[7];
    const float* edgeb = (const float*)d_in[8];
    const float* Wih   = (const float*)d_in[9];
    const float* Whh   = (const float*)d_in[10];
    const float* bih   = (const float*)d_in[11];
    const float* bhh   = (const float*)d_in[12];
    const float* fW1   = (const float*)d_in[13];
    const float* fb1   = (const float*)d_in[14];
    const float* fW2   = (const float*)d_in[15];
    const float* fb2   = (const float*)d_in[16];

    const int Nn = in_sizes[0] / 2;
    const int Ne = in_sizes[1] / 5;
    const int T  = in_sizes[2] / 3;
    const int P  = in_sizes[3] / 2;

    static bool attr_set = false;
    if (!attr_set) {
        cudaFuncSetAttribute(k1, cudaFuncAttributeMaxDynamicSharedMemorySize, K1_SMEM);
        attr_set = true;
    }

    const int GRID1 = 148;  // block 0 = LSTM, 147 = node/edge reduce
    k1<<<GRID1, NTH, K1_SMEM>>>(node, edge, hist, Nn, Ne, T,
                                nodeW, nodeb, edgeW, edgeb, Wih, Whh, bih, bhh);
    k2<<<1, 256>>>(GRID1 - 1, Nn, Ne, fW1, fb1, fW2);
    const int g3 = (P + 2047) / 2048;
    k3<<<g3, 256>>>(cand, P, Np, fb2, (float*)d_out);
}